// round 14
// baseline (speedup 1.0000x reference)
#include <cuda_runtime.h>
#include <cuda_bf16.h>
#include <cuda_fp16.h>

#define NN 100000
#define NE 1200000
#define NG 128
#define HIDN 64
#define EPSV 1e-5f
#define NSC ((NN + 1023) / 1024)   // 98 blocks (single wave: 98 < 148 SMs)

// dynamic smem for k_ngemm: Ah 8192 words | tables 320 floats
#define NGEMM_SMEM ((8192 + 320) * 4)

// ---------------- scratch ----------------
__device__ int    g_deg[NN];
__device__ int    g_rowptr[NN + 1];
__device__ int    g_wp[NN];
__device__ int    g_col[NE];
__device__ int    g_gstart[NG + 1];
__device__ int    g_bsum[NSC];
__device__ int    g_ctr;                 // reset by k_prep each launch
__device__ __half g_ylh[NN * 64];        // GEMM left output (gathered), fp16
__device__ __half g_yr[NN * 64];         // GEMM right output (self), fp16
__device__ __half g_h[NN * HIDN];        // conv output (pre-norm), fp16
__device__ __half g_xc[NN * HIDN];       // normalized activations (x1 / x2), fp16
__device__ float  g_stats[3 * NG * 128]; // per layer, per graph: [sum(64) | sumsq(64)]
__device__ float  g_pooled[NG * HIDN];
__device__ float  g_WT1[128 * 4];        // [n][k]  (n: 0..63 -> W1l, 64..127 -> W1r)
// fragment-major split-fp16 weights: index (ks*16 + jj)*32 + lane ->
//   uint4{ b0_hi, b1_hi, b0_lo, b1_lo } where n = jj*8 + lane/4, k0 = ks*16 + (lane&3)*2
__device__ uint4  g_W2f[2048];
__device__ uint4  g_W3f[2048];

// ---------------- merged prep (also resets g_ctr) ----------------
__global__ void k_prep(const int* __restrict__ batch,
                       const float* __restrict__ W1l, const float* __restrict__ W1r,
                       const float* __restrict__ W2l, const float* __restrict__ W2r,
                       const float* __restrict__ W3l, const float* __restrict__ W3r) {
    int i = blockIdx.x * blockDim.x + threadIdx.x;
    if (i < NN) {
        g_deg[i] = 0;
        int b = batch[i];
        if (i == 0 || batch[i - 1] != b) g_gstart[b] = i;
    }
    if (i == 0) { g_gstart[NG] = NN; g_ctr = 0; }
    if (i < 3 * NG * 128) g_stats[i] = 0.f;
    if (i < 512) {
        int n = i >> 2, k = i & 3;
        g_WT1[n * 4 + k] = (n < 64) ? W1l[n * 4 + k] : W1r[(n - 64) * 4 + k];
    }
    if (i < 2048) {
        int ks = i >> 9, jj = (i >> 5) & 15, lane = i & 31;
        int n = jj * 8 + (lane >> 2);
        int k0 = ks * 16 + (lane & 3) * 2;
        {
            const float* Wl = W2l; const float* Wr = W2r;
            float v00 = (n < 64) ? Wl[n * 64 + k0]     : Wr[(n - 64) * 64 + k0];
            float v01 = (n < 64) ? Wl[n * 64 + k0 + 1] : Wr[(n - 64) * 64 + k0 + 1];
            float v10 = (n < 64) ? Wl[n * 64 + k0 + 8] : Wr[(n - 64) * 64 + k0 + 8];
            float v11 = (n < 64) ? Wl[n * 64 + k0 + 9] : Wr[(n - 64) * 64 + k0 + 9];
            __half h00 = __float2half_rn(v00), h01 = __float2half_rn(v01);
            __half h10 = __float2half_rn(v10), h11 = __float2half_rn(v11);
            __half l00 = __float2half_rn(v00 - __half2float(h00));
            __half l01 = __float2half_rn(v01 - __half2float(h01));
            __half l10 = __float2half_rn(v10 - __half2float(h10));
            __half l11 = __float2half_rn(v11 - __half2float(h11));
            __half2 a = __halves2half2(h00, h01), b = __halves2half2(h10, h11);
            __half2 c = __halves2half2(l00, l01), d = __halves2half2(l10, l11);
            uint4 o;
            o.x = *(unsigned int*)&a; o.y = *(unsigned int*)&b;
            o.z = *(unsigned int*)&c; o.w = *(unsigned int*)&d;
            g_W2f[i] = o;
        }
        {
            const float* Wl = W3l; const float* Wr = W3r;
            float v00 = (n < 64) ? Wl[n * 64 + k0]     : Wr[(n - 64) * 64 + k0];
            float v01 = (n < 64) ? Wl[n * 64 + k0 + 1] : Wr[(n - 64) * 64 + k0 + 1];
            float v10 = (n < 64) ? Wl[n * 64 + k0 + 8] : Wr[(n - 64) * 64 + k0 + 8];
            float v11 = (n < 64) ? Wl[n * 64 + k0 + 9] : Wr[(n - 64) * 64 + k0 + 9];
            __half h00 = __float2half_rn(v00), h01 = __float2half_rn(v01);
            __half h10 = __float2half_rn(v10), h11 = __float2half_rn(v11);
            __half l00 = __float2half_rn(v00 - __half2float(h00));
            __half l01 = __float2half_rn(v01 - __half2float(h01));
            __half l10 = __float2half_rn(v10 - __half2float(h10));
            __half l11 = __float2half_rn(v11 - __half2float(h11));
            __half2 a = __halves2half2(h00, h01), b = __halves2half2(h10, h11);
            __half2 c = __halves2half2(l00, l01), d = __halves2half2(l10, l11);
            uint4 o;
            o.x = *(unsigned int*)&a; o.y = *(unsigned int*)&b;
            o.z = *(unsigned int*)&c; o.w = *(unsigned int*)&d;
            g_W3f[i] = o;
        }
    }
}

// ---------------- fused CSR build: hist | scan | scatter (single wave) ---------------
__device__ __forceinline__ void gbar(int k, int tid) {
    __syncthreads();
    if (tid == 0) {
        __threadfence();
        atomicAdd(&g_ctr, 1);
        while (atomicAdd(&g_ctr, 0) < k * NSC) { }
    }
    __syncthreads();
}

__global__ void __launch_bounds__(1024) k_csr(const int* __restrict__ ei) {
    __shared__ int warpsum[32];
    __shared__ int offs[4];
    __shared__ int s_off;
    int b = blockIdx.x, t = threadIdx.x, lane = t & 31, w = t >> 5;

    for (int e = b * 1024 + t; e < NE; e += NSC * 1024)
        atomicAdd(&g_deg[ei[NE + e]], 1);
    gbar(1, t);

    int i = b * 1024 + t;
    int d = (i < NN) ? g_deg[i] : 0;
    int v = d;
    #pragma unroll
    for (int o = 1; o < 32; o <<= 1) {
        int n = __shfl_up_sync(0xFFFFFFFFu, v, o);
        if (lane >= o) v += n;
    }
    if (lane == 31) warpsum[w] = v;
    __syncthreads();
    if (w == 0) {
        int s = warpsum[lane];
        #pragma unroll
        for (int o = 1; o < 32; o <<= 1) {
            int n = __shfl_up_sync(0xFFFFFFFFu, s, o);
            if (lane >= o) s += n;
        }
        warpsum[lane] = s;
        if (lane == 31) g_bsum[b] = s;
    }
    gbar(2, t);

    if (t < 128) {
        int val = (t < b && t < NSC) ? g_bsum[t] : 0;
        #pragma unroll
        for (int o = 16; o >= 1; o >>= 1) val += __shfl_xor_sync(0xFFFFFFFFu, val, o);
        if (lane == 0) offs[t >> 5] = val;
    }
    __syncthreads();
    if (t == 0) s_off = offs[0] + offs[1] + offs[2] + offs[3];
    __syncthreads();
    int ex = s_off + v - d + (w > 0 ? warpsum[w - 1] : 0);
    if (i < NN) { g_rowptr[i] = ex; g_wp[i] = ex; }
    if (i == NN - 1) g_rowptr[NN] = ex + d;
    gbar(3, t);

    for (int e = b * 1024 + t; e < NE; e += NSC * 1024) {
        int src = ei[e];
        int dst = ei[NE + e];
        int p = atomicAdd(&g_wp[dst], 1);
        g_col[p] = src;
    }
}

// ---------------- layer 1 fully fused: gather x + K=4 GEMM + stats -------------------
__global__ void __launch_bounds__(256) k_layer1(const float* __restrict__ x,
                                                const float* __restrict__ b1,
                                                const int* __restrict__ batch) {
    __shared__ float4 sA[256], sX[256];
    __shared__ float4 sW[128];
    int tid = threadIdx.x;
    if (tid < 128) sW[tid] = ((const float4*)g_WT1)[tid];
    int v = blockIdx.x * 256 + tid;
    float4 agg = make_float4(0.f, 0.f, 0.f, 0.f);
    float4 xv  = make_float4(0.f, 0.f, 0.f, 0.f);
    if (v < NN) {
        int r0 = g_rowptr[v], r1 = g_rowptr[v + 1];
        const float4* X4 = (const float4*)x;
        float4 a0 = agg, a1 = agg, a2 = agg, a3 = agg;
        int e = r0;
        for (; e + 4 <= r1; e += 4) {
            float4 p0 = X4[g_col[e]];
            float4 p1 = X4[g_col[e + 1]];
            float4 p2 = X4[g_col[e + 2]];
            float4 p3 = X4[g_col[e + 3]];
            a0.x += p0.x; a0.y += p0.y; a0.z += p0.z; a0.w += p0.w;
            a1.x += p1.x; a1.y += p1.y; a1.z += p1.z; a1.w += p1.w;
            a2.x += p2.x; a2.y += p2.y; a2.z += p2.z; a2.w += p2.w;
            a3.x += p3.x; a3.y += p3.y; a3.z += p3.z; a3.w += p3.w;
        }
        for (; e < r1; e++) {
            float4 p = X4[g_col[e]];
            a0.x += p.x; a0.y += p.y; a0.z += p.z; a0.w += p.w;
        }
        float invd = 1.0f / (float)max(r1 - r0, 1);
        agg.x = (a0.x + a1.x + a2.x + a3.x) * invd;
        agg.y = (a0.y + a1.y + a2.y + a3.y) * invd;
        agg.z = (a0.z + a1.z + a2.z + a3.z) * invd;
        agg.w = (a0.w + a1.w + a2.w + a3.w) * invd;
        xv = X4[v];
    }
    sA[tid] = agg;
    sX[tid] = xv;
    __syncthreads();

    int w = tid >> 5, l = tid & 31;
    int vb = blockIdx.x * 256 + w * 32;
    float2 bp = ((const float2*)b1)[l];
    float4 wA0 = sW[2 * l],      wA1 = sW[2 * l + 1];
    float4 wX0 = sW[64 + 2 * l], wX1 = sW[64 + 2 * l + 1];
    __half2* H = (__half2*)g_h;
    float s0 = 0.f, s1 = 0.f, q0 = 0.f, q1 = 0.f;
    int curg = -1;
    for (int vi = 0; vi < 32; vi++) {
        int vv = vb + vi;
        if (vv >= NN) break;
        int g = batch[vv];
        if (g != curg) {
            if (curg >= 0) {
                atomicAdd(&g_stats[curg * 128 + 2 * l],         s0);
                atomicAdd(&g_stats[curg * 128 + 2 * l + 1],     s1);
                atomicAdd(&g_stats[curg * 128 + 64 + 2 * l],     q0);
                atomicAdd(&g_stats[curg * 128 + 64 + 2 * l + 1], q1);
                s0 = s1 = q0 = q1 = 0.f;
            }
            curg = g;
        }
        float4 A = sA[w * 32 + vi];
        float4 X = sX[w * 32 + vi];
        float h0 = bp.x + wA0.x * A.x + wA0.y * A.y + wA0.z * A.z + wA0.w * A.w
                        + wX0.x * X.x + wX0.y * X.y + wX0.z * X.z + wX0.w * X.w;
        float h1 = bp.y + wA1.x * A.x + wA1.y * A.y + wA1.z * A.z + wA1.w * A.w
                        + wX1.x * X.x + wX1.y * X.y + wX1.z * X.z + wX1.w * X.w;
        H[vv * 32 + l] = __floats2half2_rn(h0, h1);
        s0 += h0; s1 += h1; q0 += h0 * h0; q1 += h1 * h1;
    }
    if (curg >= 0) {
        atomicAdd(&g_stats[curg * 128 + 2 * l],         s0);
        atomicAdd(&g_stats[curg * 128 + 2 * l + 1],     s1);
        atomicAdd(&g_stats[curg * 128 + 64 + 2 * l],     q0);
        atomicAdd(&g_stats[curg * 128 + 64 + 2 * l + 1], q1);
    }
}

// ---------------- gather (fp16) + bias + stats -----------------------------
__global__ void __launch_bounds__(256) k_aggstats(const int* __restrict__ batch,
                                                  const float* __restrict__ bias, int so) {
    int w = threadIdx.x >> 5, l = threadIdx.x & 31;
    int vbase = blockIdx.x * 128 + w * 16;
    float2 bp = ((const float2*)bias)[l];
    const __half2* Y  = (const __half2*)g_ylh;
    const __half2* YR = (const __half2*)g_yr;
    __half2* H = (__half2*)g_h;
    float* st = &g_stats[so];
    float s0 = 0.f, s1 = 0.f, q0 = 0.f, q1 = 0.f;
    int curg = -1;
    for (int vi = 0; vi < 16; vi++) {
        int v = vbase + vi;
        if (v >= NN) break;
        int g = batch[v];
        if (g != curg) {
            if (curg >= 0) {
                atomicAdd(&st[curg * 128 + 2 * l],         s0);
                atomicAdd(&st[curg * 128 + 2 * l + 1],     s1);
                atomicAdd(&st[curg * 128 + 64 + 2 * l],     q0);
                atomicAdd(&st[curg * 128 + 64 + 2 * l + 1], q1);
                s0 = s1 = q0 = q1 = 0.f;
            }
            curg = g;
        }
        int r0 = g_rowptr[v], r1 = g_rowptr[v + 1];
        float ax = 0.f, ay = 0.f;
        int e = r0;
        for (; e + 4 <= r1; e += 4) {
            int a = g_col[e], b = g_col[e + 1], c = g_col[e + 2], d = g_col[e + 3];
            float2 p0 = __half22float2(Y[a * 32 + l]);
            float2 p1 = __half22float2(Y[b * 32 + l]);
            float2 p2 = __half22float2(Y[c * 32 + l]);
            float2 p3 = __half22float2(Y[d * 32 + l]);
            ax += p0.x + p1.x + p2.x + p3.x;
            ay += p0.y + p1.y + p2.y + p3.y;
        }
        for (; e < r1; e++) {
            float2 p = __half22float2(Y[g_col[e] * 32 + l]);
            ax += p.x; ay += p.y;
        }
        float invd = 1.0f / (float)max(r1 - r0, 1);
        float2 yr = __half22float2(YR[v * 32 + l]);
        float hx = ax * invd + yr.x + bp.x;
        float hy = ay * invd + yr.y + bp.y;
        H[v * 32 + l] = __floats2half2_rn(hx, hy);
        s0 += hx; s1 += hy; q0 += hx * hx; q1 += hy * hy;
    }
    if (curg >= 0) {
        atomicAdd(&st[curg * 128 + 2 * l],         s0);
        atomicAdd(&st[curg * 128 + 2 * l + 1],     s1);
        atomicAdd(&st[curg * 128 + 64 + 2 * l],     q0);
        atomicAdd(&st[curg * 128 + 64 + 2 * l + 1], q1);
    }
}

#define MMA16816(ac, A0, A1, A2, A3, B0, B1)                                  \
    asm volatile("mma.sync.aligned.m16n8k16.row.col.f32.f16.f16.f32 "         \
                 "{%0,%1,%2,%3}, {%4,%5,%6,%7}, {%8,%9}, {%0,%1,%2,%3};"      \
                 : "+f"(ac[0]), "+f"(ac[1]), "+f"(ac[2]), "+f"(ac[3])         \
                 : "r"(A0), "r"(A1), "r"(A2), "r"(A3), "r"(B0), "r"(B1))

// ---------------- fused GraphNorm(+res)+ReLU + tensor-core GEMM ----------------------
// 256-row tiles (grid 391 -> single wave), 256 threads, each warp does 2 row-groups.
__global__ void __launch_bounds__(256) k_ngemm(int l3, int use_res,
        const float* __restrict__ gamma, const float* __restrict__ beta,
        const float* __restrict__ alpha, const int* __restrict__ batch, int so) {
    extern __shared__ unsigned int dsm[];
    unsigned int* Ah  = dsm;                    // 8192 words: 256 rows x 32, XOR-swizzled
    float* s_am = (float*)(dsm + 8192);         // [2][64]
    float* s_sc = s_am + 128;                   // [2][64]
    float* s_be = s_sc + 128;                   // [64]
    const uint4* GWf = l3 ? g_W3f : g_W2f;
    int tid = threadIdx.x;
    int n0 = blockIdx.x * 256;

    int g0 = batch[n0];
    int split = g_gstart[g0 + 1] - n0;      // rows >= split belong to g0+1 (tile spans <=2 graphs)
    int g1 = (g0 + 1 < NG) ? g0 + 1 : g0;
    if (tid < 128) {
        int side = tid >> 6, f = tid & 63;
        int g = side ? g1 : g0;
        float cnt = (float)(g_gstart[g + 1] - g_gstart[g]);
        float ic = 1.0f / cnt;
        float m   = g_stats[so + g * 128 + f] * ic;
        float ex2 = g_stats[so + g * 128 + 64 + f] * ic;
        float al = alpha[f];
        float var = ex2 - (2.0f * al - al * al) * m * m;
        s_sc[side * 64 + f] = gamma[f] * rsqrtf(var + EPSV);
        s_am[side * 64 + f] = al * m;
        if (side == 0) s_be[f] = beta[f];
    }
    __syncthreads();
    // norm (+res) + relu -> fp16 A tile (swizzled) + fp16 g_xc, 256 rows
    #pragma unroll
    for (int it = 0; it < 16; it++) {
        int idx = it * 1024 + tid * 4;
        int row = idx >> 6, k0 = idx & 63;
        int v = n0 + row;
        float4 hv = make_float4(0.f, 0.f, 0.f, 0.f);
        float4 rv = make_float4(0.f, 0.f, 0.f, 0.f);
        if (v < NN) {
            uint2 hraw = *(const uint2*)&g_h[v * 64 + k0];
            float2 hf0 = __half22float2(((__half2*)&hraw)[0]);
            float2 hf1 = __half22float2(((__half2*)&hraw)[1]);
            hv = make_float4(hf0.x, hf0.y, hf1.x, hf1.y);
            if (use_res) {
                uint2 rraw = *(const uint2*)&g_xc[v * 64 + k0];
                float2 rf0 = __half22float2(((__half2*)&rraw)[0]);
                float2 rf1 = __half22float2(((__half2*)&rraw)[1]);
                rv = make_float4(rf0.x, rf0.y, rf1.x, rf1.y);
            }
        }
        int side = row >= split;
        float o[4];
        #pragma unroll
        for (int j = 0; j < 4; j++) {
            float h = (&hv.x)[j];
            float val = (h - s_am[side * 64 + k0 + j]) * s_sc[side * 64 + k0 + j]
                        + s_be[k0 + j] + (&rv.x)[j];
            val = fmaxf(val, 0.f);
            o[j] = val;
        }
        int w0 = k0 >> 1;
        int mask = (row & 7) << 2;
        __half2 p0 = __floats2half2_rn(o[0], o[1]);
        __half2 p1 = __floats2half2_rn(o[2], o[3]);
        Ah[row * 32 + (w0 ^ mask)]       = *(unsigned int*)&p0;
        Ah[row * 32 + ((w0 + 1) ^ mask)] = *(unsigned int*)&p1;
        if (v < NN) {
            uint2 oo;
            ((__half2*)&oo)[0] = p0;
            ((__half2*)&oo)[1] = p1;
            *(uint2*)&g_xc[v * 64 + k0] = oo;
        }
    }
    __syncthreads();

    int lane = tid & 31, wid = tid >> 5;          // 8 warps x 32 rows (2 groups of 16)
    int grp = lane >> 2, qid = lane & 3;
    int maskA = grp << 2;

    #pragma unroll
    for (int rg = 0; rg < 2; rg++) {
        int mbase = wid * 32 + rg * 16;
        int rowA = mbase + grp;                   // rowA & 7 == grp
        int v0 = n0 + mbase + grp;
        int v1 = v0 + 8;
        #pragma unroll
        for (int nh = 0; nh < 2; nh++) {
            float acc[8][4];
            #pragma unroll
            for (int j = 0; j < 8; j++)
                #pragma unroll
                for (int c = 0; c < 4; c++) acc[j][c] = 0.f;

            #pragma unroll
            for (int ks = 0; ks < 4; ks++) {
                int wa = ks * 8 + qid;
                unsigned int a0 = Ah[rowA * 32 + (wa ^ maskA)];
                unsigned int a1 = Ah[(rowA + 8) * 32 + (wa ^ maskA)];
                unsigned int a2 = Ah[rowA * 32 + ((wa + 4) ^ maskA)];
                unsigned int a3 = Ah[(rowA + 8) * 32 + ((wa + 4) ^ maskA)];
                #pragma unroll
                for (int j = 0; j < 8; j++) {
                    int f = ks * 16 + nh * 8 + j;
                    uint4 wf = __ldg(&GWf[f * 32 + lane]);
                    MMA16816(acc[j], a0, a1, a2, a3, wf.x, wf.y);
                    MMA16816(acc[j], a0, a1, a2, a3, wf.z, wf.w);
                }
            }

            __half* OB = nh ? g_yr : g_ylh;
            #pragma unroll
            for (int j = 0; j < 8; j++) {
                int n = j * 8 + qid * 2;
                __half2 d01 = __floats2half2_rn(acc[j][0], acc[j][1]);
                __half2 d23 = __floats2half2_rn(acc[j][2], acc[j][3]);
                if (v0 < NN) *(__half2*)&OB[v0 * 64 + n] = d01;
                if (v1 < NN) *(__half2*)&OB[v1 * 64 + n] = d23;
            }
        }
    }
}

// ---------------- layer-3 norm + residual + relu + mean pool + linear head -----------
__global__ void k_norm3pool(const float* __restrict__ gamma, const float* __restrict__ beta,
                            const float* __restrict__ alpha, int so,
                            const float* __restrict__ Wlin, const float* __restrict__ blin,
                            float* __restrict__ out) {
    int g = blockIdx.x;
    int t = threadIdx.x; // 256
    int f2 = t & 31, sub = t >> 5;
    int s = g_gstart[g], e = g_gstart[g + 1];
    float cnt = (float)(e - s);
    float ic = 1.0f / cnt;
    float S0 = g_stats[so + g * 128 + 2 * f2],     S1 = g_stats[so + g * 128 + 2 * f2 + 1];
    float Q0 = g_stats[so + g * 128 + 64 + 2 * f2], Q1 = g_stats[so + g * 128 + 64 + 2 * f2 + 1];
    float al0 = alpha[2 * f2], al1 = alpha[2 * f2 + 1];
    float m0 = S0 * ic, m1 = S1 * ic;
    float var0 = Q0 * ic - (2.0f * al0 - al0 * al0) * m0 * m0;
    float var1 = Q1 * ic - (2.0f * al1 - al1 * al1) * m1 * m1;
    float inv0 = rsqrtf(var0 + EPSV), inv1 = rsqrtf(var1 + EPSV);
    float ga0 = gamma[2 * f2], ga1 = gamma[2 * f2 + 1];
    float be0 = beta[2 * f2],  be1 = beta[2 * f2 + 1];
    float am0 = al0 * m0, am1 = al1 * m1;
    const __half2* H = (const __half2*)g_h;
    const __half2* XC = (const __half2*)g_xc;
    float p0 = 0.f, p1 = 0.f;
    for (int v = s + sub; v < e; v += 8) {
        float2 hv = __half22float2(H[v * 32 + f2]);
        float2 xv = __half22float2(XC[v * 32 + f2]);
        float y0 = ga0 * (hv.x - am0) * inv0 + be0 + xv.x;
        float y1 = ga1 * (hv.y - am1) * inv1 + be1 + xv.y;
        p0 += fmaxf(y0, 0.f);
        p1 += fmaxf(y1, 0.f);
    }
    __shared__ float sh[2][256];
    __shared__ float pool[64];
    sh[0][t] = p0; sh[1][t] = p1;
    __syncthreads();
    if (sub < 2) {
        int ff = sub;
        float acc = 0.f;
        #pragma unroll
        for (int jj = 0; jj < 8; jj++) acc += sh[ff][jj * 32 + f2];
        pool[2 * f2 + ff] = acc * ic;
        g_pooled[g * 64 + 2 * f2 + ff] = acc * ic;
    }
    __syncthreads();
    if (t < 3) {
        float s0 = blin[t];
        #pragma unroll 8
        for (int ff = 0; ff < 64; ff++) s0 += pool[ff] * Wlin[t * 64 + ff];
        out[g * 3 + t] = s0;
    }
}

// ---------------- launch ----------------
extern "C" void kernel_launch(void* const* d_in, const int* in_sizes, int n_in,
                              void* d_out, int out_size) {
    const float* x     = (const float*)d_in[0];
    const int*   ei    = (const int*)d_in[1];
    const int*   batch = (const int*)d_in[2];
    const float* W1l = (const float*)d_in[3];
    const float* b1  = (const float*)d_in[4];
    const float* W1r = (const float*)d_in[5];
    const float* W2l = (const float*)d_in[6];
    const float* b2  = (const float*)d_in[7];
    const float* W2r = (const float*)d_in[8];
    const float* W3l = (const float*)d_in[9];
    const float* b3  = (const float*)d_in[10];
    const float* W3r = (const float*)d_in[11];
    const float* g1  = (const float*)d_in[12];
    const float* be1 = (const float*)d_in[13];
    const float* a1  = (const float*)d_in[14];
    const float* g2  = (const float*)d_in[15];
    const float* be2 = (const float*)d_in[16];
    const float* a2  = (const float*)d_in[17];
    const float* g3  = (const float*)d_in[18];
    const float* be3 = (const float*)d_in[19];
    const float* a3  = (const float*)d_in[20];
    const float* Wlin = (const float*)d_in[21];
    const float* blin = (const float*)d_in[22];
    float* out = (float*)d_out;

    cudaFuncSetAttribute(k_ngemm, cudaFuncAttributeMaxDynamicSharedMemorySize, NGEMM_SMEM);

    k_prep<<<(NN + 255) / 256, 256>>>(batch, W1l, W1r, W2l, W2r, W3l, W3r);
    k_csr<<<NSC, 1024>>>(ei);

    const int AGG_BLOCKS = (NN + 127) / 128;
    const int GEMM_BLOCKS = (NN + 255) / 256;

    k_layer1<<<(NN + 255) / 256, 256>>>(x, b1, batch);
    k_ngemm<<<GEMM_BLOCKS, 256, NGEMM_SMEM>>>(0, 0, g1, be1, a1, batch, 0);
    k_aggstats<<<AGG_BLOCKS, 256>>>(batch, b2, NG * 128);
    k_ngemm<<<GEMM_BLOCKS, 256, NGEMM_SMEM>>>(1, 1, g2, be2, a2, batch, NG * 128);
    k_aggstats<<<AGG_BLOCKS, 256>>>(batch, b3, 2 * NG * 128);

    k_norm3pool<<<NG, 256>>>(g3, be3, a3, 2 * NG * 128, Wlin, blin, out);
}

// round 15
// speedup vs baseline: 1.1707x; 1.1707x over previous
#include <cuda_runtime.h>
#include <cuda_bf16.h>
#include <cuda_fp16.h>

#define NN 100000
#define NE 1200000
#define NG 128
#define HIDN 64
#define EPSV 1e-5f
#define NSC ((NN + 1023) / 1024)   // 98 blocks (single wave: 98 < 148 SMs)

// dynamic smem for k_ngemm: Ah 4096 words | Stg 128*36 words | tables 320 floats
#define NGEMM_SMEM ((4096 + 128 * 36 + 320) * 4)

// ---------------- scratch ----------------
__device__ int    g_deg[NN];
__device__ int    g_rowptr[NN + 1];
__device__ int    g_wp[NN];
__device__ int    g_col[NE];
__device__ int    g_gstart[NG + 1];
__device__ int    g_bsum[NSC];
__device__ int    g_ctr;                 // reset by k_prep each launch
__device__ __half g_ylh[NN * 64];        // GEMM left output (gathered), fp16
__device__ __half g_yr[NN * 64];         // GEMM right output (self), fp16
__device__ __half g_h[NN * HIDN];        // conv output (pre-norm), fp16
__device__ __half g_xc[NN * HIDN];       // normalized activations (x1 / x2), fp16
__device__ float  g_stats[3 * NG * 128]; // per layer, per graph: [sum(64) | sumsq(64)]
__device__ float  g_pooled[NG * HIDN];
__device__ float  g_WT1[128 * 4];        // [n][k]  (n: 0..63 -> W1l, 64..127 -> W1r)
// fragment-major split-fp16 weights: index (ks*16 + jj)*32 + lane ->
//   uint4{ b0_hi, b1_hi, b0_lo, b1_lo } where n = jj*8 + lane/4, k0 = ks*16 + (lane&3)*2
__device__ uint4  g_W2f[2048];
__device__ uint4  g_W3f[2048];

// ---------------- merged prep (also resets g_ctr) ----------------
__global__ void k_prep(const int* __restrict__ batch,
                       const float* __restrict__ W1l, const float* __restrict__ W1r,
                       const float* __restrict__ W2l, const float* __restrict__ W2r,
                       const float* __restrict__ W3l, const float* __restrict__ W3r) {
    int i = blockIdx.x * blockDim.x + threadIdx.x;
    if (i < NN) {
        g_deg[i] = 0;
        int b = batch[i];
        if (i == 0 || batch[i - 1] != b) g_gstart[b] = i;
    }
    if (i == 0) { g_gstart[NG] = NN; g_ctr = 0; }
    if (i < 3 * NG * 128) g_stats[i] = 0.f;
    if (i < 512) {
        int n = i >> 2, k = i & 3;
        g_WT1[n * 4 + k] = (n < 64) ? W1l[n * 4 + k] : W1r[(n - 64) * 4 + k];
    }
    if (i < 2048) {
        int ks = i >> 9, jj = (i >> 5) & 15, lane = i & 31;
        int n = jj * 8 + (lane >> 2);
        int k0 = ks * 16 + (lane & 3) * 2;
        {
            const float* Wl = W2l; const float* Wr = W2r;
            float v00 = (n < 64) ? Wl[n * 64 + k0]     : Wr[(n - 64) * 64 + k0];
            float v01 = (n < 64) ? Wl[n * 64 + k0 + 1] : Wr[(n - 64) * 64 + k0 + 1];
            float v10 = (n < 64) ? Wl[n * 64 + k0 + 8] : Wr[(n - 64) * 64 + k0 + 8];
            float v11 = (n < 64) ? Wl[n * 64 + k0 + 9] : Wr[(n - 64) * 64 + k0 + 9];
            __half h00 = __float2half_rn(v00), h01 = __float2half_rn(v01);
            __half h10 = __float2half_rn(v10), h11 = __float2half_rn(v11);
            __half l00 = __float2half_rn(v00 - __half2float(h00));
            __half l01 = __float2half_rn(v01 - __half2float(h01));
            __half l10 = __float2half_rn(v10 - __half2float(h10));
            __half l11 = __float2half_rn(v11 - __half2float(h11));
            __half2 a = __halves2half2(h00, h01), b = __halves2half2(h10, h11);
            __half2 c = __halves2half2(l00, l01), d = __halves2half2(l10, l11);
            uint4 o;
            o.x = *(unsigned int*)&a; o.y = *(unsigned int*)&b;
            o.z = *(unsigned int*)&c; o.w = *(unsigned int*)&d;
            g_W2f[i] = o;
        }
        {
            const float* Wl = W3l; const float* Wr = W3r;
            float v00 = (n < 64) ? Wl[n * 64 + k0]     : Wr[(n - 64) * 64 + k0];
            float v01 = (n < 64) ? Wl[n * 64 + k0 + 1] : Wr[(n - 64) * 64 + k0 + 1];
            float v10 = (n < 64) ? Wl[n * 64 + k0 + 8] : Wr[(n - 64) * 64 + k0 + 8];
            float v11 = (n < 64) ? Wl[n * 64 + k0 + 9] : Wr[(n - 64) * 64 + k0 + 9];
            __half h00 = __float2half_rn(v00), h01 = __float2half_rn(v01);
            __half h10 = __float2half_rn(v10), h11 = __float2half_rn(v11);
            __half l00 = __float2half_rn(v00 - __half2float(h00));
            __half l01 = __float2half_rn(v01 - __half2float(h01));
            __half l10 = __float2half_rn(v10 - __half2float(h10));
            __half l11 = __float2half_rn(v11 - __half2float(h11));
            __half2 a = __halves2half2(h00, h01), b = __halves2half2(h10, h11);
            __half2 c = __halves2half2(l00, l01), d = __halves2half2(l10, l11);
            uint4 o;
            o.x = *(unsigned int*)&a; o.y = *(unsigned int*)&b;
            o.z = *(unsigned int*)&c; o.w = *(unsigned int*)&d;
            g_W3f[i] = o;
        }
    }
}

// ---------------- fused CSR build: hist | scan | scatter (single wave) ---------------
__device__ __forceinline__ void gbar(int k, int tid) {
    __syncthreads();
    if (tid == 0) {
        __threadfence();
        atomicAdd(&g_ctr, 1);
        while (atomicAdd(&g_ctr, 0) < k * NSC) { }
    }
    __syncthreads();
}

__global__ void __launch_bounds__(1024) k_csr(const int* __restrict__ ei) {
    __shared__ int warpsum[32];
    __shared__ int offs[4];
    __shared__ int s_off;
    int b = blockIdx.x, t = threadIdx.x, lane = t & 31, w = t >> 5;

    for (int e = b * 1024 + t; e < NE; e += NSC * 1024)
        atomicAdd(&g_deg[ei[NE + e]], 1);
    gbar(1, t);

    int i = b * 1024 + t;
    int d = (i < NN) ? g_deg[i] : 0;
    int v = d;
    #pragma unroll
    for (int o = 1; o < 32; o <<= 1) {
        int n = __shfl_up_sync(0xFFFFFFFFu, v, o);
        if (lane >= o) v += n;
    }
    if (lane == 31) warpsum[w] = v;
    __syncthreads();
    if (w == 0) {
        int s = warpsum[lane];
        #pragma unroll
        for (int o = 1; o < 32; o <<= 1) {
            int n = __shfl_up_sync(0xFFFFFFFFu, s, o);
            if (lane >= o) s += n;
        }
        warpsum[lane] = s;
        if (lane == 31) g_bsum[b] = s;
    }
    gbar(2, t);

    if (t < 128) {
        int val = (t < b && t < NSC) ? g_bsum[t] : 0;
        #pragma unroll
        for (int o = 16; o >= 1; o >>= 1) val += __shfl_xor_sync(0xFFFFFFFFu, val, o);
        if (lane == 0) offs[t >> 5] = val;
    }
    __syncthreads();
    if (t == 0) s_off = offs[0] + offs[1] + offs[2] + offs[3];
    __syncthreads();
    int ex = s_off + v - d + (w > 0 ? warpsum[w - 1] : 0);
    if (i < NN) { g_rowptr[i] = ex; g_wp[i] = ex; }
    if (i == NN - 1) g_rowptr[NN] = ex + d;
    gbar(3, t);

    for (int e = b * 1024 + t; e < NE; e += NSC * 1024) {
        int src = ei[e];
        int dst = ei[NE + e];
        int p = atomicAdd(&g_wp[dst], 1);
        g_col[p] = src;
    }
}

// ---------------- layer 1 fully fused: gather x + K=4 GEMM + stats -------------------
__global__ void __launch_bounds__(256) k_layer1(const float* __restrict__ x,
                                                const float* __restrict__ b1,
                                                const int* __restrict__ batch) {
    __shared__ float4 sA[256], sX[256];
    __shared__ float4 sW[128];
    int tid = threadIdx.x;
    if (tid < 128) sW[tid] = ((const float4*)g_WT1)[tid];
    int v = blockIdx.x * 256 + tid;
    float4 agg = make_float4(0.f, 0.f, 0.f, 0.f);
    float4 xv  = make_float4(0.f, 0.f, 0.f, 0.f);
    if (v < NN) {
        int r0 = g_rowptr[v], r1 = g_rowptr[v + 1];
        const float4* X4 = (const float4*)x;
        float4 a0 = agg, a1 = agg, a2 = agg, a3 = agg;
        int e = r0;
        for (; e + 4 <= r1; e += 4) {
            float4 p0 = X4[g_col[e]];
            float4 p1 = X4[g_col[e + 1]];
            float4 p2 = X4[g_col[e + 2]];
            float4 p3 = X4[g_col[e + 3]];
            a0.x += p0.x; a0.y += p0.y; a0.z += p0.z; a0.w += p0.w;
            a1.x += p1.x; a1.y += p1.y; a1.z += p1.z; a1.w += p1.w;
            a2.x += p2.x; a2.y += p2.y; a2.z += p2.z; a2.w += p2.w;
            a3.x += p3.x; a3.y += p3.y; a3.z += p3.z; a3.w += p3.w;
        }
        for (; e < r1; e++) {
            float4 p = X4[g_col[e]];
            a0.x += p.x; a0.y += p.y; a0.z += p.z; a0.w += p.w;
        }
        float invd = 1.0f / (float)max(r1 - r0, 1);
        agg.x = (a0.x + a1.x + a2.x + a3.x) * invd;
        agg.y = (a0.y + a1.y + a2.y + a3.y) * invd;
        agg.z = (a0.z + a1.z + a2.z + a3.z) * invd;
        agg.w = (a0.w + a1.w + a2.w + a3.w) * invd;
        xv = X4[v];
    }
    sA[tid] = agg;
    sX[tid] = xv;
    __syncthreads();

    int w = tid >> 5, l = tid & 31;
    int vb = blockIdx.x * 256 + w * 32;
    float2 bp = ((const float2*)b1)[l];
    float4 wA0 = sW[2 * l],      wA1 = sW[2 * l + 1];
    float4 wX0 = sW[64 + 2 * l], wX1 = sW[64 + 2 * l + 1];
    __half2* H = (__half2*)g_h;
    float s0 = 0.f, s1 = 0.f, q0 = 0.f, q1 = 0.f;
    int curg = -1;
    for (int vi = 0; vi < 32; vi++) {
        int vv = vb + vi;
        if (vv >= NN) break;
        int g = batch[vv];
        if (g != curg) {
            if (curg >= 0) {
                atomicAdd(&g_stats[curg * 128 + 2 * l],         s0);
                atomicAdd(&g_stats[curg * 128 + 2 * l + 1],     s1);
                atomicAdd(&g_stats[curg * 128 + 64 + 2 * l],     q0);
                atomicAdd(&g_stats[curg * 128 + 64 + 2 * l + 1], q1);
                s0 = s1 = q0 = q1 = 0.f;
            }
            curg = g;
        }
        float4 A = sA[w * 32 + vi];
        float4 X = sX[w * 32 + vi];
        float h0 = bp.x + wA0.x * A.x + wA0.y * A.y + wA0.z * A.z + wA0.w * A.w
                        + wX0.x * X.x + wX0.y * X.y + wX0.z * X.z + wX0.w * X.w;
        float h1 = bp.y + wA1.x * A.x + wA1.y * A.y + wA1.z * A.z + wA1.w * A.w
                        + wX1.x * X.x + wX1.y * X.y + wX1.z * X.z + wX1.w * X.w;
        H[vv * 32 + l] = __floats2half2_rn(h0, h1);
        s0 += h0; s1 += h1; q0 += h0 * h0; q1 += h1 * h1;
    }
    if (curg >= 0) {
        atomicAdd(&g_stats[curg * 128 + 2 * l],         s0);
        atomicAdd(&g_stats[curg * 128 + 2 * l + 1],     s1);
        atomicAdd(&g_stats[curg * 128 + 64 + 2 * l],     q0);
        atomicAdd(&g_stats[curg * 128 + 64 + 2 * l + 1], q1);
    }
}

// ---------------- gather (fp16) + bias + stats: 8 nodes/warp -------------------------
__global__ void __launch_bounds__(256) k_aggstats(const int* __restrict__ batch,
                                                  const float* __restrict__ bias, int so) {
    int w = threadIdx.x >> 5, l = threadIdx.x & 31;
    int vbase = blockIdx.x * 64 + w * 8;
    float2 bp = ((const float2*)bias)[l];
    const __half2* Y  = (const __half2*)g_ylh;
    const __half2* YR = (const __half2*)g_yr;
    __half2* H = (__half2*)g_h;
    float* st = &g_stats[so];
    float s0 = 0.f, s1 = 0.f, q0 = 0.f, q1 = 0.f;
    int curg = -1;
    for (int vi = 0; vi < 8; vi++) {
        int v = vbase + vi;
        if (v >= NN) break;
        int g = batch[v];
        if (g != curg) {
            if (curg >= 0) {
                atomicAdd(&st[curg * 128 + 2 * l],         s0);
                atomicAdd(&st[curg * 128 + 2 * l + 1],     s1);
                atomicAdd(&st[curg * 128 + 64 + 2 * l],     q0);
                atomicAdd(&st[curg * 128 + 64 + 2 * l + 1], q1);
                s0 = s1 = q0 = q1 = 0.f;
            }
            curg = g;
        }
        int r0 = g_rowptr[v], r1 = g_rowptr[v + 1];
        float ax = 0.f, ay = 0.f;
        int e = r0;
        for (; e + 4 <= r1; e += 4) {
            int a = g_col[e], b = g_col[e + 1], c = g_col[e + 2], d = g_col[e + 3];
            float2 p0 = __half22float2(Y[a * 32 + l]);
            float2 p1 = __half22float2(Y[b * 32 + l]);
            float2 p2 = __half22float2(Y[c * 32 + l]);
            float2 p3 = __half22float2(Y[d * 32 + l]);
            ax += p0.x + p1.x + p2.x + p3.x;
            ay += p0.y + p1.y + p2.y + p3.y;
        }
        for (; e < r1; e++) {
            float2 p = __half22float2(Y[g_col[e] * 32 + l]);
            ax += p.x; ay += p.y;
        }
        float invd = 1.0f / (float)max(r1 - r0, 1);
        float2 yr = __half22float2(YR[v * 32 + l]);
        float hx = ax * invd + yr.x + bp.x;
        float hy = ay * invd + yr.y + bp.y;
        H[v * 32 + l] = __floats2half2_rn(hx, hy);
        s0 += hx; s1 += hy; q0 += hx * hx; q1 += hy * hy;
    }
    if (curg >= 0) {
        atomicAdd(&st[curg * 128 + 2 * l],         s0);
        atomicAdd(&st[curg * 128 + 2 * l + 1],     s1);
        atomicAdd(&st[curg * 128 + 64 + 2 * l],     q0);
        atomicAdd(&st[curg * 128 + 64 + 2 * l + 1], q1);
    }
}

#define MMA16816(ac, A0, A1, A2, A3, B0, B1)                                  \
    asm volatile("mma.sync.aligned.m16n8k16.row.col.f32.f16.f16.f32 "         \
                 "{%0,%1,%2,%3}, {%4,%5,%6,%7}, {%8,%9}, {%0,%1,%2,%3};"      \
                 : "+f"(ac[0]), "+f"(ac[1]), "+f"(ac[2]), "+f"(ac[3])         \
                 : "r"(A0), "r"(A1), "r"(A2), "r"(A3), "r"(B0), "r"(B1))

// ---------------- fused GraphNorm(+res)+ReLU + tensor-core GEMM (R12 config) ---------
// 128-row tiles, 256 threads. Weights direct from global (L1-resident).
// Epilogue staged through padded smem -> coalesced STG.128.
__global__ void __launch_bounds__(256, 4) k_ngemm(int l3, int use_res,
        const float* __restrict__ gamma, const float* __restrict__ beta,
        const float* __restrict__ alpha, const int* __restrict__ batch, int so) {
    extern __shared__ unsigned int dsm[];
    unsigned int* Ah  = dsm;                    // 4096 words: 128 rows x 32, XOR-swizzled
    unsigned int* Stg = dsm + 4096;             // 128 rows x 36 words (pad 4)
    float* s_am = (float*)(dsm + 4096 + 4608);  // [2][64]
    float* s_sc = s_am + 128;                   // [2][64]
    float* s_be = s_sc + 128;                   // [64]
    const uint4* GWf = l3 ? g_W3f : g_W2f;
    int tid = threadIdx.x;
    int n0 = blockIdx.x * 128;

    int g0 = batch[n0];
    int split = g_gstart[g0 + 1] - n0;      // rows >= split belong to g0+1
    int g1 = (g0 + 1 < NG) ? g0 + 1 : g0;
    if (tid < 128) {
        int side = tid >> 6, f = tid & 63;
        int g = side ? g1 : g0;
        float cnt = (float)(g_gstart[g + 1] - g_gstart[g]);
        float ic = 1.0f / cnt;
        float m   = g_stats[so + g * 128 + f] * ic;
        float ex2 = g_stats[so + g * 128 + 64 + f] * ic;
        float al = alpha[f];
        float var = ex2 - (2.0f * al - al * al) * m * m;
        s_sc[side * 64 + f] = gamma[f] * rsqrtf(var + EPSV);
        s_am[side * 64 + f] = al * m;
        if (side == 0) s_be[f] = beta[f];
    }
    __syncthreads();
    // norm (+res) + relu -> fp16 A tile (swizzled) + fp16 g_xc
    #pragma unroll
    for (int it = 0; it < 8; it++) {
        int idx = it * 1024 + tid * 4;
        int row = idx >> 6, k0 = idx & 63;
        int v = n0 + row;
        float4 hv = make_float4(0.f, 0.f, 0.f, 0.f);
        float4 rv = make_float4(0.f, 0.f, 0.f, 0.f);
        if (v < NN) {
            uint2 hraw = *(const uint2*)&g_h[v * 64 + k0];
            float2 hf0 = __half22float2(((__half2*)&hraw)[0]);
            float2 hf1 = __half22float2(((__half2*)&hraw)[1]);
            hv = make_float4(hf0.x, hf0.y, hf1.x, hf1.y);
            if (use_res) {
                uint2 rraw = *(const uint2*)&g_xc[v * 64 + k0];
                float2 rf0 = __half22float2(((__half2*)&rraw)[0]);
                float2 rf1 = __half22float2(((__half2*)&rraw)[1]);
                rv = make_float4(rf0.x, rf0.y, rf1.x, rf1.y);
            }
        }
        int side = row >= split;
        float o[4];
        #pragma unroll
        for (int j = 0; j < 4; j++) {
            float h = (&hv.x)[j];
            float val = (h - s_am[side * 64 + k0 + j]) * s_sc[side * 64 + k0 + j]
                        + s_be[k0 + j] + (&rv.x)[j];
            val = fmaxf(val, 0.f);
            o[j] = val;
        }
        int w0 = k0 >> 1;
        int mask = (row & 7) << 2;
        __half2 p0 = __floats2half2_rn(o[0], o[1]);
        __half2 p1 = __floats2half2_rn(o[2], o[3]);
        Ah[row * 32 + (w0 ^ mask)]       = *(unsigned int*)&p0;
        Ah[row * 32 + ((w0 + 1) ^ mask)] = *(unsigned int*)&p1;
        if (v < NN) {
            uint2 oo;
            ((__half2*)&oo)[0] = p0;
            ((__half2*)&oo)[1] = p1;
            *(uint2*)&g_xc[v * 64 + k0] = oo;
        }
    }
    __syncthreads();

    int lane = tid & 31, wid = tid >> 5;          // 8 warps x 16 rows
    int grp = lane >> 2, qid = lane & 3;
    int mbase = wid * 16;
    int rowA = mbase + grp;                       // rowA & 7 == grp
    int maskA = grp << 2;

    #pragma unroll
    for (int nh = 0; nh < 2; nh++) {
        float acc[8][4];
        #pragma unroll
        for (int j = 0; j < 8; j++)
            #pragma unroll
            for (int c = 0; c < 4; c++) acc[j][c] = 0.f;

        #pragma unroll
        for (int ks = 0; ks < 4; ks++) {
            int wa = ks * 8 + qid;
            unsigned int a0 = Ah[rowA * 32 + (wa ^ maskA)];
            unsigned int a1 = Ah[(rowA + 8) * 32 + (wa ^ maskA)];
            unsigned int a2 = Ah[rowA * 32 + ((wa + 4) ^ maskA)];
            unsigned int a3 = Ah[(rowA + 8) * 32 + ((wa + 4) ^ maskA)];
            #pragma unroll
            for (int j = 0; j < 8; j++) {
                int f = ks * 16 + nh * 8 + j;
                uint4 wf = __ldg(&GWf[f * 32 + lane]);
                MMA16816(acc[j], a0, a1, a2, a3, wf.x, wf.y);
                MMA16816(acc[j], a0, a1, a2, a3, wf.z, wf.w);
            }
        }

        // stage accumulators to padded smem (conflict-free), then coalesced STG.128
        __syncwarp();
        #pragma unroll
        for (int j = 0; j < 8; j++) {
            int cw = j * 4 + qid;                       // column word (n/2)
            __half2 d01 = __floats2half2_rn(acc[j][0], acc[j][1]);
            __half2 d23 = __floats2half2_rn(acc[j][2], acc[j][3]);
            Stg[(mbase + grp) * 36 + cw]     = *(unsigned int*)&d01;
            Stg[(mbase + grp + 8) * 36 + cw] = *(unsigned int*)&d23;
        }
        __syncwarp();
        __half* OB = nh ? g_yr : g_ylh;
        #pragma unroll
        for (int it = 0; it < 4; it++) {
            int i = it * 32 + lane;
            int row = i >> 3, c4 = i & 7;
            int v = n0 + mbase + row;
            uint4 val = *(uint4*)&Stg[(mbase + row) * 36 + c4 * 4];
            if (v < NN) ((uint4*)&OB[v * 64])[c4] = val;
        }
    }
}

// ---------------- layer-3 norm + residual + relu + mean pool + linear head -----------
__global__ void k_norm3pool(const float* __restrict__ gamma, const float* __restrict__ beta,
                            const float* __restrict__ alpha, int so,
                            const float* __restrict__ Wlin, const float* __restrict__ blin,
                            float* __restrict__ out) {
    int g = blockIdx.x;
    int t = threadIdx.x; // 256
    int f2 = t & 31, sub = t >> 5;
    int s = g_gstart[g], e = g_gstart[g + 1];
    float cnt = (float)(e - s);
    float ic = 1.0f / cnt;
    float S0 = g_stats[so + g * 128 + 2 * f2],     S1 = g_stats[so + g * 128 + 2 * f2 + 1];
    float Q0 = g_stats[so + g * 128 + 64 + 2 * f2], Q1 = g_stats[so + g * 128 + 64 + 2 * f2 + 1];
    float al0 = alpha[2 * f2], al1 = alpha[2 * f2 + 1];
    float m0 = S0 * ic, m1 = S1 * ic;
    float var0 = Q0 * ic - (2.0f * al0 - al0 * al0) * m0 * m0;
    float var1 = Q1 * ic - (2.0f * al1 - al1 * al1) * m1 * m1;
    float inv0 = rsqrtf(var0 + EPSV), inv1 = rsqrtf(var1 + EPSV);
    float ga0 = gamma[2 * f2], ga1 = gamma[2 * f2 + 1];
    float be0 = beta[2 * f2],  be1 = beta[2 * f2 + 1];
    float am0 = al0 * m0, am1 = al1 * m1;
    const __half2* H = (const __half2*)g_h;
    const __half2* XC = (const __half2*)g_xc;
    float p0 = 0.f, p1 = 0.f;
    for (int v = s + sub; v < e; v += 8) {
        float2 hv = __half22float2(H[v * 32 + f2]);
        float2 xv = __half22float2(XC[v * 32 + f2]);
        float y0 = ga0 * (hv.x - am0) * inv0 + be0 + xv.x;
        float y1 = ga1 * (hv.y - am1) * inv1 + be1 + xv.y;
        p0 += fmaxf(y0, 0.f);
        p1 += fmaxf(y1, 0.f);
    }
    __shared__ float sh[2][256];
    __shared__ float pool[64];
    sh[0][t] = p0; sh[1][t] = p1;
    __syncthreads();
    if (sub < 2) {
        int ff = sub;
        float acc = 0.f;
        #pragma unroll
        for (int jj = 0; jj < 8; jj++) acc += sh[ff][jj * 32 + f2];
        pool[2 * f2 + ff] = acc * ic;
        g_pooled[g * 64 + 2 * f2 + ff] = acc * ic;
    }
    __syncthreads();
    if (t < 3) {
        float s0 = blin[t];
        #pragma unroll 8
        for (int ff = 0; ff < 64; ff++) s0 += pool[ff] * Wlin[t * 64 + ff];
        out[g * 3 + t] = s0;
    }
}

// ---------------- launch ----------------
extern "C" void kernel_launch(void* const* d_in, const int* in_sizes, int n_in,
                              void* d_out, int out_size) {
    const float* x     = (const float*)d_in[0];
    const int*   ei    = (const int*)d_in[1];
    const int*   batch = (const int*)d_in[2];
    const float* W1l = (const float*)d_in[3];
    const float* b1  = (const float*)d_in[4];
    const float* W1r = (const float*)d_in[5];
    const float* W2l = (const float*)d_in[6];
    const float* b2  = (const float*)d_in[7];
    const float* W2r = (const float*)d_in[8];
    const float* W3l = (const float*)d_in[9];
    const float* b3  = (const float*)d_in[10];
    const float* W3r = (const float*)d_in[11];
    const float* g1  = (const float*)d_in[12];
    const float* be1 = (const float*)d_in[13];
    const float* a1  = (const float*)d_in[14];
    const float* g2  = (const float*)d_in[15];
    const float* be2 = (const float*)d_in[16];
    const float* a2  = (const float*)d_in[17];
    const float* g3  = (const float*)d_in[18];
    const float* be3 = (const float*)d_in[19];
    const float* a3  = (const float*)d_in[20];
    const float* Wlin = (const float*)d_in[21];
    const float* blin = (const float*)d_in[22];
    float* out = (float*)d_out;

    cudaFuncSetAttribute(k_ngemm, cudaFuncAttributeMaxDynamicSharedMemorySize, NGEMM_SMEM);

    k_prep<<<(NN + 255) / 256, 256>>>(batch, W1l, W1r, W2l, W2r, W3l, W3r);
    k_csr<<<NSC, 1024>>>(ei);

    const int AGG_BLOCKS = (NN + 63) / 64;
    const int GEMM_BLOCKS = (NN + 127) / 128;

    k_layer1<<<(NN + 255) / 256, 256>>>(x, b1, batch);
    k_ngemm<<<GEMM_BLOCKS, 256, NGEMM_SMEM>>>(0, 0, g1, be1, a1, batch, 0);
    k_aggstats<<<AGG_BLOCKS, 256>>>(batch, b2, NG * 128);
    k_ngemm<<<GEMM_BLOCKS, 256, NGEMM_SMEM>>>(1, 1, g2, be2, a2, batch, NG * 128);
    k_aggstats<<<AGG_BLOCKS, 256>>>(batch, b3, 2 * NG * 128);

    k_norm3pool<<<NG, 256>>>(g3, be3, a3, 2 * NG * 128, Wlin, blin, out);
}

// round 16
// speedup vs baseline: 1.1896x; 1.0161x over previous
#include <cuda_runtime.h>
#include <cuda_bf16.h>
#include <cuda_fp16.h>

#define NN 100000
#define NE 1200000
#define NG 128
#define HIDN 64
#define EPSV 1e-5f
#define NSC ((NN + 1023) / 1024)   // 98 blocks (single wave: 98 < 148 SMs)

// dynamic smem for k_ngemm: Ah 4096 words | Stg 128*36 words | tables 320 floats
#define NGEMM_SMEM ((4096 + 128 * 36 + 320) * 4)

// ---------------- scratch ----------------
__device__ int    g_deg[NN];
__device__ int    g_rowptr[NN + 1];
__device__ int    g_wp[NN];
__device__ int    g_col[NE];
__device__ int    g_gstart[NG + 1];
__device__ int    g_bsum[NSC];
__device__ int    g_ctr;                 // reset by k_prep each launch
__device__ __half g_ylh[NN * 64];        // GEMM left output (gathered), fp16
__device__ __half g_yr[NN * 64];         // GEMM right output (self), fp16
__device__ __half g_h[NN * HIDN];        // conv output (pre-norm), fp16
__device__ __half g_xc[NN * HIDN];       // normalized activations (x1 / x2), fp16
__device__ float  g_stats[3 * NG * 128]; // per layer, per graph: [sum(64) | sumsq(64)]
__device__ float  g_pooled[NG * HIDN];
__device__ float  g_WT1[128 * 4];        // [n][k]  (n: 0..63 -> W1l, 64..127 -> W1r)
// fragment-major split-fp16 weights: index (ks*16 + jj)*32 + lane ->
//   uint4{ b0_hi, b1_hi, b0_lo, b1_lo } where n = jj*8 + lane/4, k0 = ks*16 + (lane&3)*2
__device__ uint4  g_W2f[2048];
__device__ uint4  g_W3f[2048];

// ---------------- merged prep (also resets g_ctr) ----------------
__global__ void k_prep(const int* __restrict__ batch,
                       const float* __restrict__ W1l, const float* __restrict__ W1r,
                       const float* __restrict__ W2l, const float* __restrict__ W2r,
                       const float* __restrict__ W3l, const float* __restrict__ W3r) {
    int i = blockIdx.x * blockDim.x + threadIdx.x;
    if (i < NN) {
        g_deg[i] = 0;
        int b = batch[i];
        if (i == 0 || batch[i - 1] != b) g_gstart[b] = i;
    }
    if (i == 0) { g_gstart[NG] = NN; g_ctr = 0; }
    if (i < 3 * NG * 128) g_stats[i] = 0.f;
    if (i < 512) {
        int n = i >> 2, k = i & 3;
        g_WT1[n * 4 + k] = (n < 64) ? W1l[n * 4 + k] : W1r[(n - 64) * 4 + k];
    }
    if (i < 2048) {
        int ks = i >> 9, jj = (i >> 5) & 15, lane = i & 31;
        int n = jj * 8 + (lane >> 2);
        int k0 = ks * 16 + (lane & 3) * 2;
        {
            const float* Wl = W2l; const float* Wr = W2r;
            float v00 = (n < 64) ? Wl[n * 64 + k0]     : Wr[(n - 64) * 64 + k0];
            float v01 = (n < 64) ? Wl[n * 64 + k0 + 1] : Wr[(n - 64) * 64 + k0 + 1];
            float v10 = (n < 64) ? Wl[n * 64 + k0 + 8] : Wr[(n - 64) * 64 + k0 + 8];
            float v11 = (n < 64) ? Wl[n * 64 + k0 + 9] : Wr[(n - 64) * 64 + k0 + 9];
            __half h00 = __float2half_rn(v00), h01 = __float2half_rn(v01);
            __half h10 = __float2half_rn(v10), h11 = __float2half_rn(v11);
            __half l00 = __float2half_rn(v00 - __half2float(h00));
            __half l01 = __float2half_rn(v01 - __half2float(h01));
            __half l10 = __float2half_rn(v10 - __half2float(h10));
            __half l11 = __float2half_rn(v11 - __half2float(h11));
            __half2 a = __halves2half2(h00, h01), b = __halves2half2(h10, h11);
            __half2 c = __halves2half2(l00, l01), d = __halves2half2(l10, l11);
            uint4 o;
            o.x = *(unsigned int*)&a; o.y = *(unsigned int*)&b;
            o.z = *(unsigned int*)&c; o.w = *(unsigned int*)&d;
            g_W2f[i] = o;
        }
        {
            const float* Wl = W3l; const float* Wr = W3r;
            float v00 = (n < 64) ? Wl[n * 64 + k0]     : Wr[(n - 64) * 64 + k0];
            float v01 = (n < 64) ? Wl[n * 64 + k0 + 1] : Wr[(n - 64) * 64 + k0 + 1];
            float v10 = (n < 64) ? Wl[n * 64 + k0 + 8] : Wr[(n - 64) * 64 + k0 + 8];
            float v11 = (n < 64) ? Wl[n * 64 + k0 + 9] : Wr[(n - 64) * 64 + k0 + 9];
            __half h00 = __float2half_rn(v00), h01 = __float2half_rn(v01);
            __half h10 = __float2half_rn(v10), h11 = __float2half_rn(v11);
            __half l00 = __float2half_rn(v00 - __half2float(h00));
            __half l01 = __float2half_rn(v01 - __half2float(h01));
            __half l10 = __float2half_rn(v10 - __half2float(h10));
            __half l11 = __float2half_rn(v11 - __half2float(h11));
            __half2 a = __halves2half2(h00, h01), b = __halves2half2(h10, h11);
            __half2 c = __halves2half2(l00, l01), d = __halves2half2(l10, l11);
            uint4 o;
            o.x = *(unsigned int*)&a; o.y = *(unsigned int*)&b;
            o.z = *(unsigned int*)&c; o.w = *(unsigned int*)&d;
            g_W3f[i] = o;
        }
    }
}

// ---------------- fused CSR build: hist | scan | scatter (single wave) ---------------
__device__ __forceinline__ void gbar(int k, int tid) {
    __syncthreads();
    if (tid == 0) {
        __threadfence();
        atomicAdd(&g_ctr, 1);
        while (atomicAdd(&g_ctr, 0) < k * NSC) { }
    }
    __syncthreads();
}

__global__ void __launch_bounds__(1024) k_csr(const int* __restrict__ ei) {
    __shared__ int warpsum[32];
    __shared__ int offs[4];
    __shared__ int s_off;
    int b = blockIdx.x, t = threadIdx.x, lane = t & 31, w = t >> 5;

    for (int e = b * 1024 + t; e < NE; e += NSC * 1024)
        atomicAdd(&g_deg[ei[NE + e]], 1);
    gbar(1, t);

    int i = b * 1024 + t;
    int d = (i < NN) ? g_deg[i] : 0;
    int v = d;
    #pragma unroll
    for (int o = 1; o < 32; o <<= 1) {
        int n = __shfl_up_sync(0xFFFFFFFFu, v, o);
        if (lane >= o) v += n;
    }
    if (lane == 31) warpsum[w] = v;
    __syncthreads();
    if (w == 0) {
        int s = warpsum[lane];
        #pragma unroll
        for (int o = 1; o < 32; o <<= 1) {
            int n = __shfl_up_sync(0xFFFFFFFFu, s, o);
            if (lane >= o) s += n;
        }
        warpsum[lane] = s;
        if (lane == 31) g_bsum[b] = s;
    }
    gbar(2, t);

    if (t < 128) {
        int val = (t < b && t < NSC) ? g_bsum[t] : 0;
        #pragma unroll
        for (int o = 16; o >= 1; o >>= 1) val += __shfl_xor_sync(0xFFFFFFFFu, val, o);
        if (lane == 0) offs[t >> 5] = val;
    }
    __syncthreads();
    if (t == 0) s_off = offs[0] + offs[1] + offs[2] + offs[3];
    __syncthreads();
    int ex = s_off + v - d + (w > 0 ? warpsum[w - 1] : 0);
    if (i < NN) { g_rowptr[i] = ex; g_wp[i] = ex; }
    if (i == NN - 1) g_rowptr[NN] = ex + d;
    gbar(3, t);

    for (int e = b * 1024 + t; e < NE; e += NSC * 1024) {
        int src = ei[e];
        int dst = ei[NE + e];
        int p = atomicAdd(&g_wp[dst], 1);
        g_col[p] = src;
    }
}

// ---------------- layer 1 fully fused: gather x + K=4 GEMM + stats -------------------
__global__ void __launch_bounds__(256) k_layer1(const float* __restrict__ x,
                                                const float* __restrict__ b1,
                                                const int* __restrict__ batch) {
    __shared__ float4 sA[256], sX[256];
    __shared__ float4 sW[128];
    int tid = threadIdx.x;
    if (tid < 128) sW[tid] = ((const float4*)g_WT1)[tid];
    int v = blockIdx.x * 256 + tid;
    float4 agg = make_float4(0.f, 0.f, 0.f, 0.f);
    float4 xv  = make_float4(0.f, 0.f, 0.f, 0.f);
    if (v < NN) {
        int r0 = g_rowptr[v], r1 = g_rowptr[v + 1];
        const float4* X4 = (const float4*)x;
        float4 a0 = agg, a1 = agg, a2 = agg, a3 = agg;
        int e = r0;
        for (; e + 4 <= r1; e += 4) {
            float4 p0 = X4[g_col[e]];
            float4 p1 = X4[g_col[e + 1]];
            float4 p2 = X4[g_col[e + 2]];
            float4 p3 = X4[g_col[e + 3]];
            a0.x += p0.x; a0.y += p0.y; a0.z += p0.z; a0.w += p0.w;
            a1.x += p1.x; a1.y += p1.y; a1.z += p1.z; a1.w += p1.w;
            a2.x += p2.x; a2.y += p2.y; a2.z += p2.z; a2.w += p2.w;
            a3.x += p3.x; a3.y += p3.y; a3.z += p3.z; a3.w += p3.w;
        }
        for (; e < r1; e++) {
            float4 p = X4[g_col[e]];
            a0.x += p.x; a0.y += p.y; a0.z += p.z; a0.w += p.w;
        }
        float invd = 1.0f / (float)max(r1 - r0, 1);
        agg.x = (a0.x + a1.x + a2.x + a3.x) * invd;
        agg.y = (a0.y + a1.y + a2.y + a3.y) * invd;
        agg.z = (a0.z + a1.z + a2.z + a3.z) * invd;
        agg.w = (a0.w + a1.w + a2.w + a3.w) * invd;
        xv = X4[v];
    }
    sA[tid] = agg;
    sX[tid] = xv;
    __syncthreads();

    int w = tid >> 5, l = tid & 31;
    int vb = blockIdx.x * 256 + w * 32;
    float2 bp = ((const float2*)b1)[l];
    float4 wA0 = sW[2 * l],      wA1 = sW[2 * l + 1];
    float4 wX0 = sW[64 + 2 * l], wX1 = sW[64 + 2 * l + 1];
    __half2* H = (__half2*)g_h;
    float s0 = 0.f, s1 = 0.f, q0 = 0.f, q1 = 0.f;
    int curg = -1;
    for (int vi = 0; vi < 32; vi++) {
        int vv = vb + vi;
        if (vv >= NN) break;
        int g = batch[vv];
        if (g != curg) {
            if (curg >= 0) {
                atomicAdd(&g_stats[curg * 128 + 2 * l],         s0);
                atomicAdd(&g_stats[curg * 128 + 2 * l + 1],     s1);
                atomicAdd(&g_stats[curg * 128 + 64 + 2 * l],     q0);
                atomicAdd(&g_stats[curg * 128 + 64 + 2 * l + 1], q1);
                s0 = s1 = q0 = q1 = 0.f;
            }
            curg = g;
        }
        float4 A = sA[w * 32 + vi];
        float4 X = sX[w * 32 + vi];
        float h0 = bp.x + wA0.x * A.x + wA0.y * A.y + wA0.z * A.z + wA0.w * A.w
                        + wX0.x * X.x + wX0.y * X.y + wX0.z * X.z + wX0.w * X.w;
        float h1 = bp.y + wA1.x * A.x + wA1.y * A.y + wA1.z * A.z + wA1.w * A.w
                        + wX1.x * X.x + wX1.y * X.y + wX1.z * X.z + wX1.w * X.w;
        H[vv * 32 + l] = __floats2half2_rn(h0, h1);
        s0 += h0; s1 += h1; q0 += h0 * h0; q1 += h1 * h1;
    }
    if (curg >= 0) {
        atomicAdd(&g_stats[curg * 128 + 2 * l],         s0);
        atomicAdd(&g_stats[curg * 128 + 2 * l + 1],     s1);
        atomicAdd(&g_stats[curg * 128 + 64 + 2 * l],     q0);
        atomicAdd(&g_stats[curg * 128 + 64 + 2 * l + 1], q1);
    }
}

// ---------------- gather (fp16) + bias + stats: 4 nodes/warp -------------------------
__global__ void __launch_bounds__(256) k_aggstats(const int* __restrict__ batch,
                                                  const float* __restrict__ bias, int so) {
    int w = threadIdx.x >> 5, l = threadIdx.x & 31;
    int vbase = blockIdx.x * 32 + w * 4;
    float2 bp = ((const float2*)bias)[l];
    const __half2* Y  = (const __half2*)g_ylh;
    const __half2* YR = (const __half2*)g_yr;
    __half2* H = (__half2*)g_h;
    float* st = &g_stats[so];
    float s0 = 0.f, s1 = 0.f, q0 = 0.f, q1 = 0.f;
    int curg = -1;
    for (int vi = 0; vi < 4; vi++) {
        int v = vbase + vi;
        if (v >= NN) break;
        int g = batch[v];
        if (g != curg) {
            if (curg >= 0) {
                atomicAdd(&st[curg * 128 + 2 * l],         s0);
                atomicAdd(&st[curg * 128 + 2 * l + 1],     s1);
                atomicAdd(&st[curg * 128 + 64 + 2 * l],     q0);
                atomicAdd(&st[curg * 128 + 64 + 2 * l + 1], q1);
                s0 = s1 = q0 = q1 = 0.f;
            }
            curg = g;
        }
        int r0 = g_rowptr[v], r1 = g_rowptr[v + 1];
        float ax = 0.f, ay = 0.f;
        int e = r0;
        for (; e + 4 <= r1; e += 4) {
            int a = g_col[e], b = g_col[e + 1], c = g_col[e + 2], d = g_col[e + 3];
            float2 p0 = __half22float2(Y[a * 32 + l]);
            float2 p1 = __half22float2(Y[b * 32 + l]);
            float2 p2 = __half22float2(Y[c * 32 + l]);
            float2 p3 = __half22float2(Y[d * 32 + l]);
            ax += p0.x + p1.x + p2.x + p3.x;
            ay += p0.y + p1.y + p2.y + p3.y;
        }
        for (; e < r1; e++) {
            float2 p = __half22float2(Y[g_col[e] * 32 + l]);
            ax += p.x; ay += p.y;
        }
        float invd = 1.0f / (float)max(r1 - r0, 1);
        float2 yr = __half22float2(YR[v * 32 + l]);
        float hx = ax * invd + yr.x + bp.x;
        float hy = ay * invd + yr.y + bp.y;
        H[v * 32 + l] = __floats2half2_rn(hx, hy);
        s0 += hx; s1 += hy; q0 += hx * hx; q1 += hy * hy;
    }
    if (curg >= 0) {
        atomicAdd(&st[curg * 128 + 2 * l],         s0);
        atomicAdd(&st[curg * 128 + 2 * l + 1],     s1);
        atomicAdd(&st[curg * 128 + 64 + 2 * l],     q0);
        atomicAdd(&st[curg * 128 + 64 + 2 * l + 1], q1);
    }
}

#define MMA16816(ac, A0, A1, A2, A3, B0, B1)                                  \
    asm volatile("mma.sync.aligned.m16n8k16.row.col.f32.f16.f16.f32 "         \
                 "{%0,%1,%2,%3}, {%4,%5,%6,%7}, {%8,%9}, {%0,%1,%2,%3};"      \
                 : "+f"(ac[0]), "+f"(ac[1]), "+f"(ac[2]), "+f"(ac[3])         \
                 : "r"(A0), "r"(A1), "r"(A2), "r"(A3), "r"(B0), "r"(B1))

// ---------------- fused GraphNorm(+res)+ReLU + tensor-core GEMM (R12 config) ---------
__global__ void __launch_bounds__(256, 4) k_ngemm(int l3, int use_res,
        const float* __restrict__ gamma, const float* __restrict__ beta,
        const float* __restrict__ alpha, const int* __restrict__ batch, int so) {
    extern __shared__ unsigned int dsm[];
    unsigned int* Ah  = dsm;                    // 4096 words: 128 rows x 32, XOR-swizzled
    unsigned int* Stg = dsm + 4096;             // 128 rows x 36 words (pad 4)
    float* s_am = (float*)(dsm + 4096 + 4608);  // [2][64]
    float* s_sc = s_am + 128;                   // [2][64]
    float* s_be = s_sc + 128;                   // [64]
    const uint4* GWf = l3 ? g_W3f : g_W2f;
    int tid = threadIdx.x;
    int n0 = blockIdx.x * 128;

    int g0 = batch[n0];
    int split = g_gstart[g0 + 1] - n0;
    int g1 = (g0 + 1 < NG) ? g0 + 1 : g0;
    if (tid < 128) {
        int side = tid >> 6, f = tid & 63;
        int g = side ? g1 : g0;
        float cnt = (float)(g_gstart[g + 1] - g_gstart[g]);
        float ic = 1.0f / cnt;
        float m   = g_stats[so + g * 128 + f] * ic;
        float ex2 = g_stats[so + g * 128 + 64 + f] * ic;
        float al = alpha[f];
        float var = ex2 - (2.0f * al - al * al) * m * m;
        s_sc[side * 64 + f] = gamma[f] * rsqrtf(var + EPSV);
        s_am[side * 64 + f] = al * m;
        if (side == 0) s_be[f] = beta[f];
    }
    __syncthreads();
    #pragma unroll
    for (int it = 0; it < 8; it++) {
        int idx = it * 1024 + tid * 4;
        int row = idx >> 6, k0 = idx & 63;
        int v = n0 + row;
        float4 hv = make_float4(0.f, 0.f, 0.f, 0.f);
        float4 rv = make_float4(0.f, 0.f, 0.f, 0.f);
        if (v < NN) {
            uint2 hraw = *(const uint2*)&g_h[v * 64 + k0];
            float2 hf0 = __half22float2(((__half2*)&hraw)[0]);
            float2 hf1 = __half22float2(((__half2*)&hraw)[1]);
            hv = make_float4(hf0.x, hf0.y, hf1.x, hf1.y);
            if (use_res) {
                uint2 rraw = *(const uint2*)&g_xc[v * 64 + k0];
                float2 rf0 = __half22float2(((__half2*)&rraw)[0]);
                float2 rf1 = __half22float2(((__half2*)&rraw)[1]);
                rv = make_float4(rf0.x, rf0.y, rf1.x, rf1.y);
            }
        }
        int side = row >= split;
        float o[4];
        #pragma unroll
        for (int j = 0; j < 4; j++) {
            float h = (&hv.x)[j];
            float val = (h - s_am[side * 64 + k0 + j]) * s_sc[side * 64 + k0 + j]
                        + s_be[k0 + j] + (&rv.x)[j];
            val = fmaxf(val, 0.f);
            o[j] = val;
        }
        int w0 = k0 >> 1;
        int mask = (row & 7) << 2;
        __half2 p0 = __floats2half2_rn(o[0], o[1]);
        __half2 p1 = __floats2half2_rn(o[2], o[3]);
        Ah[row * 32 + (w0 ^ mask)]       = *(unsigned int*)&p0;
        Ah[row * 32 + ((w0 + 1) ^ mask)] = *(unsigned int*)&p1;
        if (v < NN) {
            uint2 oo;
            ((__half2*)&oo)[0] = p0;
            ((__half2*)&oo)[1] = p1;
            *(uint2*)&g_xc[v * 64 + k0] = oo;
        }
    }
    __syncthreads();

    int lane = tid & 31, wid = tid >> 5;          // 8 warps x 16 rows
    int grp = lane >> 2, qid = lane & 3;
    int mbase = wid * 16;
    int rowA = mbase + grp;                       // rowA & 7 == grp
    int maskA = grp << 2;

    #pragma unroll
    for (int nh = 0; nh < 2; nh++) {
        float acc[8][4];
        #pragma unroll
        for (int j = 0; j < 8; j++)
            #pragma unroll
            for (int c = 0; c < 4; c++) acc[j][c] = 0.f;

        #pragma unroll
        for (int ks = 0; ks < 4; ks++) {
            int wa = ks * 8 + qid;
            unsigned int a0 = Ah[rowA * 32 + (wa ^ maskA)];
            unsigned int a1 = Ah[(rowA + 8) * 32 + (wa ^ maskA)];
            unsigned int a2 = Ah[rowA * 32 + ((wa + 4) ^ maskA)];
            unsigned int a3 = Ah[(rowA + 8) * 32 + ((wa + 4) ^ maskA)];
            #pragma unroll
            for (int j = 0; j < 8; j++) {
                int f = ks * 16 + nh * 8 + j;
                uint4 wf = __ldg(&GWf[f * 32 + lane]);
                MMA16816(acc[j], a0, a1, a2, a3, wf.x, wf.y);
                MMA16816(acc[j], a0, a1, a2, a3, wf.z, wf.w);
            }
        }

        __syncwarp();
        #pragma unroll
        for (int j = 0; j < 8; j++) {
            int cw = j * 4 + qid;
            __half2 d01 = __floats2half2_rn(acc[j][0], acc[j][1]);
            __half2 d23 = __floats2half2_rn(acc[j][2], acc[j][3]);
            Stg[(mbase + grp) * 36 + cw]     = *(unsigned int*)&d01;
            Stg[(mbase + grp + 8) * 36 + cw] = *(unsigned int*)&d23;
        }
        __syncwarp();
        __half* OB = nh ? g_yr : g_ylh;
        #pragma unroll
        for (int it = 0; it < 4; it++) {
            int i = it * 32 + lane;
            int row = i >> 3, c4 = i & 7;
            int v = n0 + mbase + row;
            uint4 val = *(uint4*)&Stg[(mbase + row) * 36 + c4 * 4];
            if (v < NN) ((uint4*)&OB[v * 64])[c4] = val;
        }
    }
}

// ---------------- layer-3 norm + residual + relu + mean pool + linear head -----------
__global__ void k_norm3pool(const float* __restrict__ gamma, const float* __restrict__ beta,
                            const float* __restrict__ alpha, int so,
                            const float* __restrict__ Wlin, const float* __restrict__ blin,
                            float* __restrict__ out) {
    int g = blockIdx.x;
    int t = threadIdx.x; // 256
    int f2 = t & 31, sub = t >> 5;
    int s = g_gstart[g], e = g_gstart[g + 1];
    float cnt = (float)(e - s);
    float ic = 1.0f / cnt;
    float S0 = g_stats[so + g * 128 + 2 * f2],     S1 = g_stats[so + g * 128 + 2 * f2 + 1];
    float Q0 = g_stats[so + g * 128 + 64 + 2 * f2], Q1 = g_stats[so + g * 128 + 64 + 2 * f2 + 1];
    float al0 = alpha[2 * f2], al1 = alpha[2 * f2 + 1];
    float m0 = S0 * ic, m1 = S1 * ic;
    float var0 = Q0 * ic - (2.0f * al0 - al0 * al0) * m0 * m0;
    float var1 = Q1 * ic - (2.0f * al1 - al1 * al1) * m1 * m1;
    float inv0 = rsqrtf(var0 + EPSV), inv1 = rsqrtf(var1 + EPSV);
    float ga0 = gamma[2 * f2], ga1 = gamma[2 * f2 + 1];
    float be0 = beta[2 * f2],  be1 = beta[2 * f2 + 1];
    float am0 = al0 * m0, am1 = al1 * m1;
    const __half2* H = (const __half2*)g_h;
    const __half2* XC = (const __half2*)g_xc;
    float p0 = 0.f, p1 = 0.f;
    for (int v = s + sub; v < e; v += 8) {
        float2 hv = __half22float2(H[v * 32 + f2]);
        float2 xv = __half22float2(XC[v * 32 + f2]);
        float y0 = ga0 * (hv.x - am0) * inv0 + be0 + xv.x;
        float y1 = ga1 * (hv.y - am1) * inv1 + be1 + xv.y;
        p0 += fmaxf(y0, 0.f);
        p1 += fmaxf(y1, 0.f);
    }
    __shared__ float sh[2][256];
    __shared__ float pool[64];
    sh[0][t] = p0; sh[1][t] = p1;
    __syncthreads();
    if (sub < 2) {
        int ff = sub;
        float acc = 0.f;
        #pragma unroll
        for (int jj = 0; jj < 8; jj++) acc += sh[ff][jj * 32 + f2];
        pool[2 * f2 + ff] = acc * ic;
        g_pooled[g * 64 + 2 * f2 + ff] = acc * ic;
    }
    __syncthreads();
    if (t < 3) {
        float s0 = blin[t];
        #pragma unroll 8
        for (int ff = 0; ff < 64; ff++) s0 += pool[ff] * Wlin[t * 64 + ff];
        out[g * 3 + t] = s0;
    }
}

// ---------------- launch ----------------
extern "C" void kernel_launch(void* const* d_in, const int* in_sizes, int n_in,
                              void* d_out, int out_size) {
    const float* x     = (const float*)d_in[0];
    const int*   ei    = (const int*)d_in[1];
    const int*   batch = (const int*)d_in[2];
    const float* W1l = (const float*)d_in[3];
    const float* b1  = (const float*)d_in[4];
    const float* W1r = (const float*)d_in[5];
    const float* W2l = (const float*)d_in[6];
    const float* b2  = (const float*)d_in[7];
    const float* W2r = (const float*)d_in[8];
    const float* W3l = (const float*)d_in[9];
    const float* b3  = (const float*)d_in[10];
    const float* W3r = (const float*)d_in[11];
    const float* g1  = (const float*)d_in[12];
    const float* be1 = (const float*)d_in[13];
    const float* a1  = (const float*)d_in[14];
    const float* g2  = (const float*)d_in[15];
    const float* be2 = (const float*)d_in[16];
    const float* a2  = (const float*)d_in[17];
    const float* g3  = (const float*)d_in[18];
    const float* be3 = (const float*)d_in[19];
    const float* a3  = (const float*)d_in[20];
    const float* Wlin = (const float*)d_in[21];
    const float* blin = (const float*)d_in[22];
    float* out = (float*)d_out;

    cudaFuncSetAttribute(k_ngemm, cudaFuncAttributeMaxDynamicSharedMemorySize, NGEMM_SMEM);

    k_prep<<<(NN + 255) / 256, 256>>>(batch, W1l, W1r, W2l, W2r, W3l, W3r);
    k_csr<<<NSC, 1024>>>(ei);

    const int AGG_BLOCKS = (NN + 31) / 32;
    const int GEMM_BLOCKS = (NN + 127) / 128;

    k_layer1<<<(NN + 255) / 256, 256>>>(x, b1, batch);
    k_ngemm<<<GEMM_BLOCKS, 256, NGEMM_SMEM>>>(0, 0, g1, be1, a1, batch, 0);
    k_aggstats<<<AGG_BLOCKS, 256>>>(batch, b2, NG * 128);
    k_ngemm<<<GEMM_BLOCKS, 256, NGEMM_SMEM>>>(1, 1, g2, be2, a2, batch, NG * 128);
    k_aggstats<<<AGG_BLOCKS, 256>>>(batch, b3, 2 * NG * 128);

    k_norm3pool<<<NG, 256>>>(g3, be3, a3, 2 * NG * 128, Wlin, blin, out);
}